// round 3
// baseline (speedup 1.0000x reference)
#include <cuda_runtime.h>

static constexpr int NCOLS = 99;
static constexpr int TPB   = 256;   // threads per block
static constexpr int TILE  = 256;   // rows per CTA (one thread per row for the log step)
static constexpr int SEGW  = 9;     // 8 blocks + 1 pad word -> conflict-free

// ---------------- device scratch (memset-initialized, no allocation) -------
struct Zeros {
    double   acc[3];       // [0]=mse sum, [1]=dot sum, [2]=lse sum
    unsigned hist[200];    // [sex(2)][feat(10)][bin(10)]
    unsigned maxkey[10];
    unsigned done[2];      // [0]: k_prep grid sync, [1]: k_main finalize ticket
};
__device__ Zeros gz;
__device__ unsigned g_minkey[10];   // memset 0xFF

// col -> block id (0..7) for CE columns, 255 for continuous (MSE) columns
__constant__ unsigned char c_blk[NCOLS] = {
    255,                                        // 0
    0,0,0,0,0,0,0,                              // 1-7
    1,1,1,1,1,1,1,1,1,1,1,1,1,1,1,1,            // 8-23
    2,2,2,2,2,2,2,                              // 24-30
    3,3,3,3,3,3,3,3,3,3,3,3,3,3,                // 31-44
    4,4,4,4,4,4,                                // 45-50
    5,5,                                        // 51-52
    6,6,                                        // 53-54
    255,255,255,                                // 55-57
    7,7,7,7,7,7,7,7,7,7,7,7,7,7,7,7,7,7,7,7,   // 58-77
    7,7,7,7,7,7,7,7,7,7,7,7,7,7,7,7,7,7,7,7,7  // 78-98
};

// monotonic float<->uint key
__device__ __forceinline__ unsigned f2key(float f) {
    unsigned u = __float_as_uint(f);
    return (u & 0x80000000u) ? ~u : (u | 0x80000000u);
}
__device__ __forceinline__ float key2f(unsigned k) {
    unsigned u = (k & 0x80000000u) ? (k ^ 0x80000000u) : ~k;
    return __uint_as_float(u);
}

// ---------------- k_prep: minmax -> grid-sync -> histogram -----------------
__global__ void __launch_bounds__(256)
k_prep(const float4* __restrict__ e4, int B) {
    __shared__ float s_mn[8][10], s_mx[8][10];
    __shared__ unsigned sh[200];
    __shared__ float smn[10], swid[10];
    const int t = threadIdx.x, lane = t & 31, w = t >> 5;
    const int stride = gridDim.x * blockDim.x;
    const int gbase  = blockIdx.x * blockDim.x + t;

    float mn[10], mx[10];
    const float INF = __int_as_float(0x7f800000);
#pragma unroll
    for (int i = 0; i < 10; i++) { mn[i] = INF; mx[i] = -INF; }
    for (int r = gbase; r < B; r += stride) {
        float4 a = e4[3*r], b = e4[3*r+1], c = e4[3*r+2];
        float v[10] = {a.x,a.y,a.z,a.w,b.x,b.y,b.z,b.w,c.x,c.y};
#pragma unroll
        for (int i = 0; i < 10; i++) {
            mn[i] = fminf(mn[i], v[i]);
            mx[i] = fmaxf(mx[i], v[i]);
        }
    }
#pragma unroll
    for (int i = 0; i < 10; i++) {
#pragma unroll
        for (int o = 16; o > 0; o >>= 1) {
            mn[i] = fminf(mn[i], __shfl_xor_sync(0xFFFFFFFFu, mn[i], o));
            mx[i] = fmaxf(mx[i], __shfl_xor_sync(0xFFFFFFFFu, mx[i], o));
        }
    }
    if (lane == 0) {
#pragma unroll
        for (int i = 0; i < 10; i++) { s_mn[w][i] = mn[i]; s_mx[w][i] = mx[i]; }
    }
    if (t < 200) sh[t] = 0u;
    __syncthreads();
    if (t < 10) {
        float m = s_mn[0][t], x = s_mx[0][t];
#pragma unroll
        for (int ww = 1; ww < 8; ww++) { m = fminf(m, s_mn[ww][t]); x = fmaxf(x, s_mx[ww][t]); }
        atomicMin(&g_minkey[t], f2key(m));
        atomicMax(&gz.maxkey[t], f2key(x));
    }

    __threadfence();
    __syncthreads();
    if (t == 0) {
        atomicAdd(&gz.done[0], 1u);
        while (atomicAdd(&gz.done[0], 0u) < gridDim.x) __nanosleep(64);
    }
    __syncthreads();
    __threadfence();

    if (t < 10) {
        float m = key2f(g_minkey[t]);
        float x = key2f(gz.maxkey[t]);
        smn[t]  = m;
        swid[t] = fmaxf(x - m, 1e-12f);
    }
    __syncthreads();

    const int B_al = B & ~31;
    for (int r = gbase; r < B_al; r += stride) {
        float4 a = e4[3*r], b = e4[3*r+1], c = e4[3*r+2];
        unsigned base = (c.w == 0.0f) ? 0u : 100u;   // col 11 = sex
        float v[10] = {a.x,a.y,a.z,a.w,b.x,b.y,b.z,b.w,c.x,c.y};
#pragma unroll
        for (int i = 0; i < 10; i++) {
            float tt = (v[i] - smn[i]) / swid[i] * 10.0f;
            int bi = (int)floorf(tt);
            bi = bi < 0 ? 0 : (bi > 9 ? 9 : bi);
            unsigned key = base + (unsigned)(i * 10 + bi);
            unsigned msk = __match_any_sync(0xFFFFFFFFu, key);
            if ((msk & ((1u << lane) - 1u)) == 0u)
                atomicAdd(&sh[key], (unsigned)__popc(msk));
        }
    }
    for (int r = B_al + gbase; r < B; r += stride) {
        float4 a = e4[3*r], b = e4[3*r+1], c = e4[3*r+2];
        unsigned base = (c.w == 0.0f) ? 0u : 100u;
        float v[10] = {a.x,a.y,a.z,a.w,b.x,b.y,b.z,b.w,c.x,c.y};
#pragma unroll
        for (int i = 0; i < 10; i++) {
            float tt = (v[i] - smn[i]) / swid[i] * 10.0f;
            int bi = (int)floorf(tt);
            bi = bi < 0 ? 0 : (bi > 9 ? 9 : bi);
            atomicAdd(&sh[base + (unsigned)(i * 10 + bi)], 1u);
        }
    }
    __syncthreads();
    if (t < 200 && sh[t]) atomicAdd(&gz.hist[t], sh[t]);
}

// ---------------- k_main: single streaming pass ----------------------------
struct AccState {
    float mse, dot;
    float run;        // pending exp-sum for current (row,block) segment
    int   runaddr;    // word address in seg[], -1 = none
};

__device__ __forceinline__ void proc_f4(
    int idx, float4 d, float4 t, const unsigned char* __restrict__ s_blk,
    float* __restrict__ seg, AccState& st)
{
    int e = 4 * idx;
    int r = e / NCOLS;
    int c = e - r * NCOLS;
    float dv[4] = {d.x, d.y, d.z, d.w};
    float tv[4] = {t.x, t.y, t.z, t.w};
#pragma unroll
    for (int j = 0; j < 4; j++) {
        int b = s_blk[c];
        if (b == 255) {
            float df = dv[j] - tv[j];
            st.mse = fmaf(df, df, st.mse);
        } else {
            st.dot = fmaf(dv[j], tv[j], st.dot);
            float ex = __expf(dv[j]);
            int addr = r * SEGW + b;
            if (addr == st.runaddr) {
                st.run += ex;
            } else {
                if (st.runaddr >= 0) atomicAdd(&seg[st.runaddr], st.run);
                st.runaddr = addr;
                st.run = ex;
            }
        }
        if (++c == NCOLS) { c = 0; r++; }
    }
}

__global__ void __launch_bounds__(TPB)
k_main(const float* __restrict__ dec, const float* __restrict__ tru,
       float* __restrict__ out, int B) {
    __shared__ float seg[TILE * SEGW];            // 9216 B
    __shared__ unsigned char s_blk[128];
    __shared__ float wr[3][TPB / 32];
    __shared__ int   s_last;

    // init shared
    for (int i = threadIdx.x; i < TILE * SEGW; i += TPB) seg[i] = 0.f;
    if (threadIdx.x < NCOLS) s_blk[threadIdx.x] = c_blk[threadIdx.x];
    __syncthreads();

    const int r0   = blockIdx.x * TILE;
    const int rows = min(TILE, B - r0);
    const int nflt = rows * NCOLS;
    const int n4   = nflt >> 2;
    const size_t ebase = (size_t)r0 * NCOLS;
    const float4* d4 = (const float4*)(dec + ebase);
    const float4* t4 = (const float4*)(tru + ebase);

    AccState st = {0.f, 0.f, 0.f, -1};

    int i = threadIdx.x;
    for (; i + 3 * TPB < n4; i += 4 * TPB) {
        float4 dd[4], tt[4];
#pragma unroll
        for (int k = 0; k < 4; k++) { dd[k] = d4[i + k*TPB]; tt[k] = t4[i + k*TPB]; }
#pragma unroll
        for (int k = 0; k < 4; k++)
            proc_f4(i + k*TPB, dd[k], tt[k], s_blk, seg, st);
    }
    for (; i < n4; i += TPB) {
        proc_f4(i, d4[i], t4[i], s_blk, seg, st);
    }
    for (int e = (n4 << 2) + threadIdx.x; e < nflt; e += TPB) {   // float tail
        float d = dec[ebase + e], t = tru[ebase + e];
        int c = e % NCOLS, r = e / NCOLS;
        int b = s_blk[c];
        if (b == 255) { float df = d - t; st.mse = fmaf(df, df, st.mse); }
        else {
            st.dot = fmaf(d, t, st.dot);
            atomicAdd(&seg[r * SEGW + b], __expf(d));
        }
    }
    if (st.runaddr >= 0) atomicAdd(&seg[st.runaddr], st.run);
    __syncthreads();

    // log step: one thread per row, 8 logs
    float a_lse = 0.f;
    if (threadIdx.x < rows) {
        const float* s = seg + threadIdx.x * SEGW;
#pragma unroll
        for (int b = 0; b < 8; b++) a_lse += __logf(s[b]);
    }

    // block reduce -> double global atomics
    float a_mse = st.mse, a_dot = st.dot;
#pragma unroll
    for (int o = 16; o > 0; o >>= 1) {
        a_mse += __shfl_xor_sync(0xFFFFFFFFu, a_mse, o);
        a_dot += __shfl_xor_sync(0xFFFFFFFFu, a_dot, o);
        a_lse += __shfl_xor_sync(0xFFFFFFFFu, a_lse, o);
    }
    int wid = threadIdx.x >> 5, lid = threadIdx.x & 31;
    if (lid == 0) { wr[0][wid] = a_mse; wr[1][wid] = a_dot; wr[2][wid] = a_lse; }
    __syncthreads();
    if (threadIdx.x == 0) {
        float m = 0.f, d = 0.f, l = 0.f;
#pragma unroll
        for (int k = 0; k < TPB / 32; k++) { m += wr[0][k]; d += wr[1][k]; l += wr[2][k]; }
        atomicAdd(&gz.acc[0], (double)m);
        atomicAdd(&gz.acc[1], (double)d);
        atomicAdd(&gz.acc[2], (double)l);
        __threadfence();
        unsigned tk = atomicAdd(&gz.done[1], 1u);
        s_last = (tk == gridDim.x - 1u) ? 1 : 0;
    }
    __syncthreads();

    // last CTA finalizes
    if (s_last && threadIdx.x < 32) {
        __threadfence();
        int lane32 = threadIdx.x;
        double mcnt = (lane32 < 10) ? (double)gz.hist[lane32]       : 0.0;
        double fcnt = (lane32 < 10) ? (double)gz.hist[100 + lane32] : 0.0;
#pragma unroll
        for (int o = 16; o > 0; o >>= 1) {
            mcnt += __shfl_xor_sync(0xFFFFFFFFu, mcnt, o);
            fcnt += __shfl_xor_sync(0xFFFFFFFFu, fcnt, o);
        }
        double mc = fmax(mcnt, 1.0), fc = fmax(fcnt, 1.0);
        double kld = 0.0;
#pragma unroll
        for (int k = 0; k < 4; k++) {
            int b = k * 32 + lane32;
            if (b < 100) {
                double p = (double)gz.hist[b] / mc;
                double q = (double)gz.hist[100 + b] / fc;
                if (p > 0.0 && q > 0.0) kld += p * log(p / q);
            }
        }
#pragma unroll
        for (int o = 16; o > 0; o >>= 1)
            kld += __shfl_xor_sync(0xFFFFFFFFu, kld, o);
        if (lane32 == 0) {
            double mseS = atomicAdd(&gz.acc[0], 0.0);
            double dotS = atomicAdd(&gz.acc[1], 0.0);
            double lseS = atomicAdd(&gz.acc[2], 0.0);
            double fB   = (double)B;
            double mse  = mseS / fB;
            double ce   = (lseS - dotS) / fB;
            double akld = 0.5 * kld;
            out[0] = (float)(0.5 * (mse + ce) + akld);
            out[1] = (float)mse;
            out[2] = (float)ce;
            out[3] = (float)akld;
        }
    }
}

// ---------------- launcher ----------------
extern "C" void kernel_launch(void* const* d_in, const int* in_sizes, int n_in,
                              void* d_out, int out_size) {
    const float* enc = (const float*)d_in[0];   // [B,12]
    const float* dec = (const float*)d_in[1];   // [B,99]
    const float* tru = (const float*)d_in[2];   // [B,99]
    const int B = in_sizes[1] / NCOLS;
    float* out = (float*)d_out;

    void *pz = nullptr, *pk = nullptr;
    cudaGetSymbolAddress(&pz, gz);
    cudaGetSymbolAddress(&pk, g_minkey);
    cudaMemsetAsync(pz, 0, sizeof(Zeros), 0);
    cudaMemsetAsync(pk, 0xFF, 10 * sizeof(unsigned), 0);

    k_prep<<<296, 256>>>((const float4*)enc, B);

    const int grid = (B + TILE - 1) / TILE;
    k_main<<<grid, TPB>>>(dec, tru, out, B);
}

// round 4
// speedup vs baseline: 1.3830x; 1.3830x over previous
#include <cuda_runtime.h>

static constexpr int NCOLS = 99;
static constexpr int TPB   = 128;   // threads per block, k_main
static constexpr int TILE  = 128;   // rows per tile
static constexpr int NB    = 4;     // float4-pairs per pipeline batch (8 LDG.128)

// ---------------- device scratch (single memset(0), no allocation) ---------
struct Zeros {
    double   acc[3];        // [0]=mse sum, [1]=dot sum (ce cols), [2]=lse sum
    unsigned hist[200];     // [sex(2)][feat(10)][bin(10)]
    unsigned maxkey[10];    // atomicMax of key(x)
    unsigned cominkey[10];  // atomicMax of ~key(x)  (== complemented min)
    unsigned done[2];       // [0]: k_prep grid sync, [1]: k_main finalize ticket
};
__device__ Zeros gz;

// monotonic float<->uint key
__device__ __forceinline__ unsigned f2key(float f) {
    unsigned u = __float_as_uint(f);
    return (u & 0x80000000u) ? ~u : (u | 0x80000000u);
}
__device__ __forceinline__ float key2f(unsigned k) {
    unsigned u = (k & 0x80000000u) ? (k ^ 0x80000000u) : ~k;
    return __uint_as_float(u);
}

// ---------------- k_prep: minmax -> grid-sync -> histogram -----------------
__global__ void __launch_bounds__(256)
k_prep(const float4* __restrict__ e4, int B) {
    __shared__ float s_mn[8][10], s_mx[8][10];
    __shared__ unsigned sh[200];
    __shared__ float smn[10], swid[10];
    const int t = threadIdx.x, lane = t & 31, w = t >> 5;
    const int stride = gridDim.x * blockDim.x;
    const int gbase  = blockIdx.x * blockDim.x + t;

    // --- phase A: per-column min/max of encoded[:, 0:10], 2 rows per iter ---
    float mn[10], mx[10];
    const float INF = __int_as_float(0x7f800000);
#pragma unroll
    for (int i = 0; i < 10; i++) { mn[i] = INF; mx[i] = -INF; }
    for (int r = gbase; r < B; r += 2 * stride) {
        float4 a0 = e4[3*r], b0 = e4[3*r+1], c0 = e4[3*r+2];
        int r1 = r + stride;
        bool ok1 = r1 < B;
        float4 a1, b1, c1;
        if (ok1) { a1 = e4[3*r1]; b1 = e4[3*r1+1]; c1 = e4[3*r1+2]; }
        float v0[10] = {a0.x,a0.y,a0.z,a0.w,b0.x,b0.y,b0.z,b0.w,c0.x,c0.y};
#pragma unroll
        for (int i = 0; i < 10; i++) {
            mn[i] = fminf(mn[i], v0[i]);
            mx[i] = fmaxf(mx[i], v0[i]);
        }
        if (ok1) {
            float v1[10] = {a1.x,a1.y,a1.z,a1.w,b1.x,b1.y,b1.z,b1.w,c1.x,c1.y};
#pragma unroll
            for (int i = 0; i < 10; i++) {
                mn[i] = fminf(mn[i], v1[i]);
                mx[i] = fmaxf(mx[i], v1[i]);
            }
        }
    }
#pragma unroll
    for (int i = 0; i < 10; i++) {
#pragma unroll
        for (int o = 16; o > 0; o >>= 1) {
            mn[i] = fminf(mn[i], __shfl_xor_sync(0xFFFFFFFFu, mn[i], o));
            mx[i] = fmaxf(mx[i], __shfl_xor_sync(0xFFFFFFFFu, mx[i], o));
        }
    }
    if (lane == 0) {
#pragma unroll
        for (int i = 0; i < 10; i++) { s_mn[w][i] = mn[i]; s_mx[w][i] = mx[i]; }
    }
    if (t < 200) sh[t] = 0u;
    __syncthreads();
    if (t < 10) {
        float m = s_mn[0][t], x = s_mx[0][t];
#pragma unroll
        for (int ww = 1; ww < 8; ww++) { m = fminf(m, s_mn[ww][t]); x = fmaxf(x, s_mx[ww][t]); }
        atomicMax(&gz.cominkey[t], ~f2key(m));
        atomicMax(&gz.maxkey[t],    f2key(x));
    }

    // --- grid sync (all 296 CTAs resident: 2 per SM) ---
    __threadfence();
    __syncthreads();
    if (t == 0) {
        atomicAdd(&gz.done[0], 1u);
        while (atomicAdd(&gz.done[0], 0u) < gridDim.x) __nanosleep(64);
    }
    __syncthreads();
    __threadfence();

    // --- phase B: histogram with warp-aggregated shared atomics ---
    if (t < 10) {
        float m = key2f(~gz.cominkey[t]);
        float x = key2f( gz.maxkey[t]);
        smn[t]  = m;
        swid[t] = fmaxf(x - m, 1e-12f);
    }
    __syncthreads();

    const int B_al = B & ~31;
    for (int r = gbase; r < B_al; r += stride) {
        float4 a = e4[3*r], b = e4[3*r+1], c = e4[3*r+2];
        unsigned base = (c.w == 0.0f) ? 0u : 100u;   // col 11 = sex
        float v[10] = {a.x,a.y,a.z,a.w,b.x,b.y,b.z,b.w,c.x,c.y};
#pragma unroll
        for (int i = 0; i < 10; i++) {
            float tt = (v[i] - smn[i]) / swid[i] * 10.0f;   // jnp op order
            int bi = (int)floorf(tt);
            bi = bi < 0 ? 0 : (bi > 9 ? 9 : bi);
            unsigned key = base + (unsigned)(i * 10 + bi);
            unsigned msk = __match_any_sync(0xFFFFFFFFu, key);
            if ((msk & ((1u << lane) - 1u)) == 0u)
                atomicAdd(&sh[key], (unsigned)__popc(msk));
        }
    }
    for (int r = B_al + gbase; r < B; r += stride) {
        float4 a = e4[3*r], b = e4[3*r+1], c = e4[3*r+2];
        unsigned base = (c.w == 0.0f) ? 0u : 100u;
        float v[10] = {a.x,a.y,a.z,a.w,b.x,b.y,b.z,b.w,c.x,c.y};
#pragma unroll
        for (int i = 0; i < 10; i++) {
            float tt = (v[i] - smn[i]) / swid[i] * 10.0f;
            int bi = (int)floorf(tt);
            bi = bi < 0 ? 0 : (bi > 9 ? 9 : bi);
            atomicAdd(&sh[base + (unsigned)(i * 10 + bi)], 1u);
        }
    }
    __syncthreads();
    if (t < 200 && sh[t]) atomicAdd(&gz.hist[t], sh[t]);
}

// ---------------- k_main helpers -------------------------------------------
template <int S, int E>
__device__ __forceinline__ float lse_blk(const float* row) {
    float s = 0.f;
#pragma unroll
    for (int c = S; c < E; ++c) s += __expf(row[c]);
    return __logf(s);
}

// quad starting at column c0 contains a continuous column?
__device__ __forceinline__ bool quad_rare(int c0) {
    return (c0 == 0) | ((unsigned)(c0 - 52) <= 5u) | (c0 >= 96);
}

// consume one float4-pair: STS + dotAll FFMAs + rare continuous-col fixup
__device__ __forceinline__ void consume(
    float4 d, float4 t, int c0, float4* s4loc,
    float& dot0, float& dot1, float& mse, float& dotc)
{
    *s4loc = d;
    dot0 = fmaf(d.x, t.x, dot0);
    dot1 = fmaf(d.y, t.y, dot1);
    dot0 = fmaf(d.z, t.z, dot0);
    dot1 = fmaf(d.w, t.w, dot1);
    if (quad_rare(c0)) {
        float dv[4] = {d.x, d.y, d.z, d.w};
        float tv[4] = {t.x, t.y, t.z, t.w};
        int c = c0;
#pragma unroll
        for (int j = 0; j < 4; j++) {
            bool cont = (c == 0) | ((unsigned)(c - 55) <= 2u);
            if (cont) {
                float df = dv[j] - tv[j];
                mse  = fmaf(df, df, mse);
                dotc = fmaf(dv[j], tv[j], dotc);   // to subtract later
            }
            if (++c == NCOLS) c = 0;
        }
    }
}

__device__ __forceinline__ int wrap99(int c) { return (c >= NCOLS) ? c - NCOLS : c; }

// ---------------- k_main: staged stream + lse, last-CTA finalize -----------
__global__ void __launch_bounds__(TPB, 4)
k_main(const float* __restrict__ dec, const float* __restrict__ tru,
       float* __restrict__ out, int B) {
    extern __shared__ float sm[];                  // TILE*99 floats
    __shared__ float wr[3][TPB / 32];
    __shared__ int   s_last;

    const int r0   = blockIdx.x * TILE;
    const int rows = min(TILE, B - r0);
    const int nflt = rows * NCOLS;
    const int n4   = nflt >> 2;
    const size_t ebase = (size_t)r0 * NCOLS;
    const float4* d4 = (const float4*)(dec + ebase);
    const float4* t4 = (const float4*)(tru + ebase);
    float4* s4 = (float4*)sm;

    float dot0 = 0.f, dot1 = 0.f, a_mse = 0.f, dotc = 0.f;

    // column offsets: element index = 4*i; per k-slot +512 floats -> +17 mod 99
    // per batch step (+4*TPB float4 = +2048 floats) -> +68 mod 99
    int cbase = (4 * threadIdx.x) % NCOLS;

    const int step = NB * TPB;
    int i = threadIdx.x;
    float4 dd[NB], tt[NB];
    bool have = (i + (NB - 1) * TPB) < n4;
    if (have) {
#pragma unroll
        for (int k = 0; k < NB; k++) { dd[k] = d4[i + k*TPB]; tt[k] = t4[i + k*TPB]; }
    }
    while (have) {
        const int inext = i + step;
        const bool haven = (inext + (NB - 1) * TPB) < n4;
        float4 nd[NB], nt[NB];
        if (haven) {
#pragma unroll
            for (int k = 0; k < NB; k++) { nd[k] = d4[inext + k*TPB]; nt[k] = t4[inext + k*TPB]; }
        }
        int ck = cbase;
#pragma unroll
        for (int k = 0; k < NB; k++) {
            consume(dd[k], tt[k], ck, &s4[i + k*TPB], dot0, dot1, a_mse, dotc);
            ck = wrap99(ck + 17);
        }
        cbase = wrap99(cbase + 68);
        if (haven) {
#pragma unroll
            for (int k = 0; k < NB; k++) { dd[k] = nd[k]; tt[k] = nt[k]; }
        }
        i = inext;
        have = haven;
    }
    // float4 remainder
    for (; i < n4; i += TPB) {
        int c0 = (4 * i) % NCOLS;
        consume(d4[i], t4[i], c0, &s4[i], dot0, dot1, a_mse, dotc);
    }
    // float tail (none when rows*99 % 4 == 0)
    for (int e = (n4 << 2) + threadIdx.x; e < nflt; e += TPB) {
        float d = dec[ebase + e], t = tru[ebase + e];
        sm[e] = d;
        int c = e % NCOLS;
        bool cont = (c == 0) | ((unsigned)(c - 55) <= 2u);
        dot0 = fmaf(d, t, dot0);
        if (cont) {
            float df = d - t;
            a_mse = fmaf(df, df, a_mse);
            dotc  = fmaf(d, t, dotc);
        }
    }
    __syncthreads();

    // phase 2: one thread per row, 8 block-LSEs from smem (stride 99 -> conflict-free)
    float a_lse = 0.f;
    if (threadIdx.x < rows) {
        const float* row = sm + threadIdx.x * NCOLS;
        a_lse += lse_blk< 1,  8>(row);
        a_lse += lse_blk< 8, 24>(row);
        a_lse += lse_blk<24, 31>(row);
        a_lse += lse_blk<31, 45>(row);
        a_lse += lse_blk<45, 51>(row);
        a_lse += lse_blk<51, 53>(row);
        a_lse += lse_blk<53, 55>(row);
        a_lse += lse_blk<58, 99>(row);
    }

    // block reduce -> double global atomics
    float a_dot = (dot0 + dot1) - dotc;
#pragma unroll
    for (int o = 16; o > 0; o >>= 1) {
        a_mse += __shfl_xor_sync(0xFFFFFFFFu, a_mse, o);
        a_dot += __shfl_xor_sync(0xFFFFFFFFu, a_dot, o);
        a_lse += __shfl_xor_sync(0xFFFFFFFFu, a_lse, o);
    }
    int wid = threadIdx.x >> 5, lid = threadIdx.x & 31;
    if (lid == 0) { wr[0][wid] = a_mse; wr[1][wid] = a_dot; wr[2][wid] = a_lse; }
    __syncthreads();
    if (threadIdx.x == 0) {
        float m = 0.f, d = 0.f, l = 0.f;
#pragma unroll
        for (int k = 0; k < TPB / 32; k++) { m += wr[0][k]; d += wr[1][k]; l += wr[2][k]; }
        atomicAdd(&gz.acc[0], (double)m);
        atomicAdd(&gz.acc[1], (double)d);
        atomicAdd(&gz.acc[2], (double)l);
        __threadfence();
        unsigned tk = atomicAdd(&gz.done[1], 1u);
        s_last = (tk == gridDim.x - 1u) ? 1 : 0;
    }
    __syncthreads();

    // last CTA finalizes (double precision, 32 lanes)
    if (s_last && threadIdx.x < 32) {
        __threadfence();
        int lane32 = threadIdx.x;
        double mcnt = (lane32 < 10) ? (double)gz.hist[lane32]       : 0.0;
        double fcnt = (lane32 < 10) ? (double)gz.hist[100 + lane32] : 0.0;
#pragma unroll
        for (int o = 16; o > 0; o >>= 1) {
            mcnt += __shfl_xor_sync(0xFFFFFFFFu, mcnt, o);
            fcnt += __shfl_xor_sync(0xFFFFFFFFu, fcnt, o);
        }
        double mc = fmax(mcnt, 1.0), fc = fmax(fcnt, 1.0);
        double kld = 0.0;
#pragma unroll
        for (int k = 0; k < 4; k++) {
            int b = k * 32 + lane32;
            if (b < 100) {
                double p = (double)gz.hist[b] / mc;
                double q = (double)gz.hist[100 + b] / fc;
                if (p > 0.0 && q > 0.0) kld += p * log(p / q);
            }
        }
#pragma unroll
        for (int o = 16; o > 0; o >>= 1)
            kld += __shfl_xor_sync(0xFFFFFFFFu, kld, o);
        if (lane32 == 0) {
            double mseS = atomicAdd(&gz.acc[0], 0.0);
            double dotS = atomicAdd(&gz.acc[1], 0.0);
            double lseS = atomicAdd(&gz.acc[2], 0.0);
            double fB   = (double)B;
            double mse  = mseS / fB;
            double ce   = (lseS - dotS) / fB;
            double akld = 0.5 * kld;
            out[0] = (float)(0.5 * (mse + ce) + akld);
            out[1] = (float)mse;
            out[2] = (float)ce;
            out[3] = (float)akld;
        }
    }
}

// ---------------- launcher ----------------
extern "C" void kernel_launch(void* const* d_in, const int* in_sizes, int n_in,
                              void* d_out, int out_size) {
    const float* enc = (const float*)d_in[0];   // [B,12]
    const float* dec = (const float*)d_in[1];   // [B,99]
    const float* tru = (const float*)d_in[2];   // [B,99]
    const int B = in_sizes[1] / NCOLS;
    float* out = (float*)d_out;

    void* pz = nullptr;
    cudaGetSymbolAddress(&pz, gz);
    cudaMemsetAsync(pz, 0, sizeof(Zeros), 0);

    k_prep<<<296, 256>>>((const float4*)enc, B);

    const int smem = TILE * NCOLS * (int)sizeof(float);   // 50688 B
    cudaFuncSetAttribute(k_main, cudaFuncAttributeMaxDynamicSharedMemorySize, smem);
    const int grid = (B + TILE - 1) / TILE;
    k_main<<<grid, TPB, smem>>>(dec, tru, out, B);
}

// round 5
// speedup vs baseline: 1.4926x; 1.0793x over previous
#include <cuda_runtime.h>
#include <cuda_fp16.h>

static constexpr int NCOLS = 99;
static constexpr int TPB   = 128;   // threads per block, k_main
static constexpr int TILE  = 128;   // rows per tile

// ---------------- device scratch (single memset(0), no allocation) ---------
struct Zeros {
    double   acc[3];        // [0]=mse sum, [1]=dot sum (ce cols), [2]=lse sum
    unsigned hist[200];     // [sex(2)][feat(10)][bin(10)]
    unsigned maxkey[10];    // atomicMax of key(x)
    unsigned cominkey[10];  // atomicMax of ~key(x)  (== complemented min)
    unsigned done[2];       // [0]: k_prep grid sync, [1]: k_main finalize ticket
};
__device__ Zeros gz;

// monotonic float<->uint key
__device__ __forceinline__ unsigned f2key(float f) {
    unsigned u = __float_as_uint(f);
    return (u & 0x80000000u) ? ~u : (u | 0x80000000u);
}
__device__ __forceinline__ float key2f(unsigned k) {
    unsigned u = (k & 0x80000000u) ? (k ^ 0x80000000u) : ~k;
    return __uint_as_float(u);
}

// ---------------- k_prep: minmax -> grid-sync -> histogram -----------------
__global__ void __launch_bounds__(256)
k_prep(const float4* __restrict__ e4, int B) {
    __shared__ float s_mn[8][10], s_mx[8][10];
    __shared__ unsigned sh[200];
    __shared__ float smn[10], swid[10];
    const int t = threadIdx.x, lane = t & 31, w = t >> 5;
    const int stride = gridDim.x * blockDim.x;
    const int gbase  = blockIdx.x * blockDim.x + t;

    float mn[10], mx[10];
    const float INF = __int_as_float(0x7f800000);
#pragma unroll
    for (int i = 0; i < 10; i++) { mn[i] = INF; mx[i] = -INF; }
    for (int r = gbase; r < B; r += 2 * stride) {
        float4 a0 = e4[3*r], b0 = e4[3*r+1], c0 = e4[3*r+2];
        int r1 = r + stride;
        bool ok1 = r1 < B;
        float4 a1, b1, c1;
        if (ok1) { a1 = e4[3*r1]; b1 = e4[3*r1+1]; c1 = e4[3*r1+2]; }
        float v0[10] = {a0.x,a0.y,a0.z,a0.w,b0.x,b0.y,b0.z,b0.w,c0.x,c0.y};
#pragma unroll
        for (int i = 0; i < 10; i++) {
            mn[i] = fminf(mn[i], v0[i]);
            mx[i] = fmaxf(mx[i], v0[i]);
        }
        if (ok1) {
            float v1[10] = {a1.x,a1.y,a1.z,a1.w,b1.x,b1.y,b1.z,b1.w,c1.x,c1.y};
#pragma unroll
            for (int i = 0; i < 10; i++) {
                mn[i] = fminf(mn[i], v1[i]);
                mx[i] = fmaxf(mx[i], v1[i]);
            }
        }
    }
#pragma unroll
    for (int i = 0; i < 10; i++) {
#pragma unroll
        for (int o = 16; o > 0; o >>= 1) {
            mn[i] = fminf(mn[i], __shfl_xor_sync(0xFFFFFFFFu, mn[i], o));
            mx[i] = fmaxf(mx[i], __shfl_xor_sync(0xFFFFFFFFu, mx[i], o));
        }
    }
    if (lane == 0) {
#pragma unroll
        for (int i = 0; i < 10; i++) { s_mn[w][i] = mn[i]; s_mx[w][i] = mx[i]; }
    }
    if (t < 200) sh[t] = 0u;
    __syncthreads();
    if (t < 10) {
        float m = s_mn[0][t], x = s_mx[0][t];
#pragma unroll
        for (int ww = 1; ww < 8; ww++) { m = fminf(m, s_mn[ww][t]); x = fmaxf(x, s_mx[ww][t]); }
        atomicMax(&gz.cominkey[t], ~f2key(m));
        atomicMax(&gz.maxkey[t],    f2key(x));
    }

    __threadfence();
    __syncthreads();
    if (t == 0) {
        atomicAdd(&gz.done[0], 1u);
        while (atomicAdd(&gz.done[0], 0u) < gridDim.x) __nanosleep(64);
    }
    __syncthreads();
    __threadfence();

    if (t < 10) {
        float m = key2f(~gz.cominkey[t]);
        float x = key2f( gz.maxkey[t]);
        smn[t]  = m;
        swid[t] = fmaxf(x - m, 1e-12f);
    }
    __syncthreads();

    const int B_al = B & ~31;
    for (int r = gbase; r < B_al; r += stride) {
        float4 a = e4[3*r], b = e4[3*r+1], c = e4[3*r+2];
        unsigned base = (c.w == 0.0f) ? 0u : 100u;   // col 11 = sex
        float v[10] = {a.x,a.y,a.z,a.w,b.x,b.y,b.z,b.w,c.x,c.y};
#pragma unroll
        for (int i = 0; i < 10; i++) {
            float tt = (v[i] - smn[i]) / swid[i] * 10.0f;   // jnp op order
            int bi = (int)floorf(tt);
            bi = bi < 0 ? 0 : (bi > 9 ? 9 : bi);
            unsigned key = base + (unsigned)(i * 10 + bi);
            unsigned msk = __match_any_sync(0xFFFFFFFFu, key);
            if ((msk & ((1u << lane) - 1u)) == 0u)
                atomicAdd(&sh[key], (unsigned)__popc(msk));
        }
    }
    for (int r = B_al + gbase; r < B; r += stride) {
        float4 a = e4[3*r], b = e4[3*r+1], c = e4[3*r+2];
        unsigned base = (c.w == 0.0f) ? 0u : 100u;
        float v[10] = {a.x,a.y,a.z,a.w,b.x,b.y,b.z,b.w,c.x,c.y};
#pragma unroll
        for (int i = 0; i < 10; i++) {
            float tt = (v[i] - smn[i]) / swid[i] * 10.0f;
            int bi = (int)floorf(tt);
            bi = bi < 0 ? 0 : (bi > 9 ? 9 : bi);
            atomicAdd(&sh[base + (unsigned)(i * 10 + bi)], 1u);
        }
    }
    __syncthreads();
    if (t < 200 && sh[t]) atomicAdd(&gz.hist[t], sh[t]);
}

// ---------------- k_main helpers -------------------------------------------
template <int S, int E>
__device__ __forceinline__ float lse_blk_h(const __half* row) {
    float s = 0.f;
#pragma unroll
    for (int c = S; c < E; ++c) s += __expf(__half2float(row[c]));
    return __logf(s);
}

__device__ __forceinline__ bool quad_rare(int c0) {
    return (c0 == 0) | ((unsigned)(c0 - 52) <= 5u) | (c0 >= 96);
}
__device__ __forceinline__ int wrap99(int c) { return (c >= NCOLS) ? c - NCOLS : c; }

// consume one float4-pair: fp16 store + dotAll FFMAs + rare cont-col fixup
__device__ __forceinline__ void consume(
    float4 d, float4 t, int c0, __half* smh, int i,
    float& dot0, float& dot1, float& mse, float& dotc)
{
    union { __half2 h[2]; uint2 u; } pk;
    pk.h[0] = __floats2half2_rn(d.x, d.y);
    pk.h[1] = __floats2half2_rn(d.z, d.w);
    *reinterpret_cast<uint2*>(smh + 4 * i) = pk.u;   // 8B aligned
    dot0 = fmaf(d.x, t.x, dot0);
    dot1 = fmaf(d.y, t.y, dot1);
    dot0 = fmaf(d.z, t.z, dot0);
    dot1 = fmaf(d.w, t.w, dot1);
    if (quad_rare(c0)) {
        float dv[4] = {d.x, d.y, d.z, d.w};
        float tv[4] = {t.x, t.y, t.z, t.w};
        int c = c0;
#pragma unroll
        for (int j = 0; j < 4; j++) {
            bool cont = (c == 0) | ((unsigned)(c - 55) <= 2u);
            if (cont) {
                float df = dv[j] - tv[j];
                mse  = fmaf(df, df, mse);
                dotc = fmaf(dv[j], tv[j], dotc);   // subtract later
            }
            if (++c == NCOLS) c = 0;
        }
    }
}

// ---------------- k_main: fp16-staged stream + lse, last-CTA finalize ------
__global__ void __launch_bounds__(TPB, 6)
k_main(const float* __restrict__ dec, const float* __restrict__ tru,
       float* __restrict__ out, int B) {
    __shared__ __half smh[TILE * NCOLS];     // 25344 B
    __shared__ float wr[3][TPB / 32];
    __shared__ int   s_last;

    const int r0   = blockIdx.x * TILE;
    const int rows = min(TILE, B - r0);
    const int nflt = rows * NCOLS;
    const int n4   = nflt >> 2;
    const size_t ebase = (size_t)r0 * NCOLS;
    const float4* d4 = (const float4*)(dec + ebase);
    const float4* t4 = (const float4*)(tru + ebase);

    float dot0 = 0.f, dot1 = 0.f, a_mse = 0.f, dotc = 0.f;

    // columns: element 4*(tid + j*TPB): +17 mod 99 per j, +34 per 2-pair stage
    int cb = (4 * threadIdx.x) % NCOLS;
    const int NS = n4 / (2 * TPB);           // full 2-pair stages (uniform)

    float4 da0, ta0, da1, ta1, db0, tb0, db1, tb1;
    int ia = threadIdx.x;
    if (NS > 0) {
        da0 = d4[ia];       ta0 = t4[ia];
        da1 = d4[ia + TPB]; ta1 = t4[ia + TPB];
    }
    for (int s = 0; s < NS; s += 2) {
        const int ib = ia + 2 * TPB;
        const bool hb = (s + 1) < NS;
        if (hb) { db0 = d4[ib]; tb0 = t4[ib]; db1 = d4[ib + TPB]; tb1 = t4[ib + TPB]; }
        consume(da0, ta0, cb,             smh, ia,       dot0, dot1, a_mse, dotc);
        consume(da1, ta1, wrap99(cb + 17), smh, ia + TPB, dot0, dot1, a_mse, dotc);
        cb = wrap99(cb + 34);
        if (!hb) break;
        const int ic = ib + 2 * TPB;
        const bool hc = (s + 2) < NS;
        if (hc) { da0 = d4[ic]; ta0 = t4[ic]; da1 = d4[ic + TPB]; ta1 = t4[ic + TPB]; }
        consume(db0, tb0, cb,             smh, ib,       dot0, dot1, a_mse, dotc);
        consume(db1, tb1, wrap99(cb + 17), smh, ib + TPB, dot0, dot1, a_mse, dotc);
        cb = wrap99(cb + 34);
        ia = ic;
    }
    // float4 remainder
    for (int i = NS * 2 * TPB + threadIdx.x; i < n4; i += TPB) {
        consume(d4[i], t4[i], (4 * i) % NCOLS, smh, i, dot0, dot1, a_mse, dotc);
    }
    // float tail (none when rows*99 % 4 == 0)
    for (int e = (n4 << 2) + threadIdx.x; e < nflt; e += TPB) {
        float d = dec[ebase + e], t = tru[ebase + e];
        smh[e] = __float2half_rn(d);
        int c = e % NCOLS;
        bool cont = (c == 0) | ((unsigned)(c - 55) <= 2u);
        dot0 = fmaf(d, t, dot0);
        if (cont) {
            float df = d - t;
            a_mse = fmaf(df, df, a_mse);
            dotc  = fmaf(d, t, dotc);
        }
    }
    __syncthreads();

    // phase 2: one thread per row, 8 block-LSEs from fp16 smem
    float a_lse = 0.f;
    if (threadIdx.x < rows) {
        const __half* row = smh + threadIdx.x * NCOLS;
        a_lse += lse_blk_h< 1,  8>(row);
        a_lse += lse_blk_h< 8, 24>(row);
        a_lse += lse_blk_h<24, 31>(row);
        a_lse += lse_blk_h<31, 45>(row);
        a_lse += lse_blk_h<45, 51>(row);
        a_lse += lse_blk_h<51, 53>(row);
        a_lse += lse_blk_h<53, 55>(row);
        a_lse += lse_blk_h<58, 99>(row);
    }

    // block reduce -> double global atomics
    float a_dot = (dot0 + dot1) - dotc;
#pragma unroll
    for (int o = 16; o > 0; o >>= 1) {
        a_mse += __shfl_xor_sync(0xFFFFFFFFu, a_mse, o);
        a_dot += __shfl_xor_sync(0xFFFFFFFFu, a_dot, o);
        a_lse += __shfl_xor_sync(0xFFFFFFFFu, a_lse, o);
    }
    int wid = threadIdx.x >> 5, lid = threadIdx.x & 31;
    if (lid == 0) { wr[0][wid] = a_mse; wr[1][wid] = a_dot; wr[2][wid] = a_lse; }
    __syncthreads();
    if (threadIdx.x == 0) {
        float m = 0.f, d = 0.f, l = 0.f;
#pragma unroll
        for (int k = 0; k < TPB / 32; k++) { m += wr[0][k]; d += wr[1][k]; l += wr[2][k]; }
        atomicAdd(&gz.acc[0], (double)m);
        atomicAdd(&gz.acc[1], (double)d);
        atomicAdd(&gz.acc[2], (double)l);
        __threadfence();
        unsigned tk = atomicAdd(&gz.done[1], 1u);
        s_last = (tk == gridDim.x - 1u) ? 1 : 0;
    }
    __syncthreads();

    // last CTA finalizes (double precision, 32 lanes)
    if (s_last && threadIdx.x < 32) {
        __threadfence();
        int lane32 = threadIdx.x;
        double mcnt = (lane32 < 10) ? (double)gz.hist[lane32]       : 0.0;
        double fcnt = (lane32 < 10) ? (double)gz.hist[100 + lane32] : 0.0;
#pragma unroll
        for (int o = 16; o > 0; o >>= 1) {
            mcnt += __shfl_xor_sync(0xFFFFFFFFu, mcnt, o);
            fcnt += __shfl_xor_sync(0xFFFFFFFFu, fcnt, o);
        }
        double mc = fmax(mcnt, 1.0), fc = fmax(fcnt, 1.0);
        double kld = 0.0;
#pragma unroll
        for (int k = 0; k < 4; k++) {
            int b = k * 32 + lane32;
            if (b < 100) {
                double p = (double)gz.hist[b] / mc;
                double q = (double)gz.hist[100 + b] / fc;
                if (p > 0.0 && q > 0.0) kld += p * log(p / q);
            }
        }
#pragma unroll
        for (int o = 16; o > 0; o >>= 1)
            kld += __shfl_xor_sync(0xFFFFFFFFu, kld, o);
        if (lane32 == 0) {
            double mseS = atomicAdd(&gz.acc[0], 0.0);
            double dotS = atomicAdd(&gz.acc[1], 0.0);
            double lseS = atomicAdd(&gz.acc[2], 0.0);
            double fB   = (double)B;
            double mse  = mseS / fB;
            double ce   = (lseS - dotS) / fB;
            double akld = 0.5 * kld;
            out[0] = (float)(0.5 * (mse + ce) + akld);
            out[1] = (float)mse;
            out[2] = (float)ce;
            out[3] = (float)akld;
        }
    }
}

// ---------------- launcher ----------------
extern "C" void kernel_launch(void* const* d_in, const int* in_sizes, int n_in,
                              void* d_out, int out_size) {
    const float* enc = (const float*)d_in[0];   // [B,12]
    const float* dec = (const float*)d_in[1];   // [B,99]
    const float* tru = (const float*)d_in[2];   // [B,99]
    const int B = in_sizes[1] / NCOLS;
    float* out = (float*)d_out;

    void* pz = nullptr;
    cudaGetSymbolAddress(&pz, gz);
    cudaMemsetAsync(pz, 0, sizeof(Zeros), 0);

    k_prep<<<296, 256>>>((const float4*)enc, B);

    const int grid = (B + TILE - 1) / TILE;
    k_main<<<grid, TPB>>>(dec, tru, out, B);
}

// round 7
// speedup vs baseline: 1.6757x; 1.1226x over previous
#include <cuda_runtime.h>
#include <cuda_fp16.h>

static constexpr int NCOLS = 99;
static constexpr int TPB   = 128;   // threads per block
static constexpr int TILE  = 128;   // rows per tile
static constexpr int NPREP = 296;   // prep-role CTAs (first in grid)

// ---------------- device scratch (single memset(0), no allocation) ---------
struct Zeros {
    double   acc[3];        // [0]=mse sum, [1]=dot sum (ce cols), [2]=lse sum
    unsigned hist[200];     // [sex(2)][feat(10)][bin(10)]
    unsigned maxkey[10];    // atomicMax of key(x)
    unsigned cominkey[10];  // atomicMax of ~key(x)  (== complemented min)
    unsigned done[3];       // [0]: prep minmax sync, [1]: tile ticket, [2]: prep hist done
};
__device__ Zeros gz;

// monotonic float<->uint key
__device__ __forceinline__ unsigned f2key(float f) {
    unsigned u = __float_as_uint(f);
    return (u & 0x80000000u) ? ~u : (u | 0x80000000u);
}
__device__ __forceinline__ float key2f(unsigned k) {
    unsigned u = (k & 0x80000000u) ? (k ^ 0x80000000u) : ~k;
    return __uint_as_float(u);
}

// ---------------- helpers ---------------------------------------------------
template <int S, int E>
__device__ __forceinline__ float lse_blk_h(const __half* row) {
    float s = 0.f;
#pragma unroll
    for (int c = S; c < E; ++c) s += __expf(__half2float(row[c]));
    return __logf(s);
}

__device__ __forceinline__ bool quad_rare(int c0) {
    return (c0 == 0) | ((unsigned)(c0 - 52) <= 5u) | (c0 >= 96);
}
__device__ __forceinline__ int wrap99(int c) { return (c >= NCOLS) ? c - NCOLS : c; }

// consume one float4-pair: fp16 store + dotAll FFMAs + rare cont-col fixup
__device__ __forceinline__ void consume(
    float4 d, float4 t, int c0, __half* smh, int i,
    float& dot0, float& dot1, float& mse, float& dotc)
{
    union { __half2 h[2]; uint2 u; } pk;
    pk.h[0] = __floats2half2_rn(d.x, d.y);
    pk.h[1] = __floats2half2_rn(d.z, d.w);
    *reinterpret_cast<uint2*>(smh + 4 * i) = pk.u;   // 8B aligned
    dot0 = fmaf(d.x, t.x, dot0);
    dot1 = fmaf(d.y, t.y, dot1);
    dot0 = fmaf(d.z, t.z, dot0);
    dot1 = fmaf(d.w, t.w, dot1);
    if (quad_rare(c0)) {
        float dv[4] = {d.x, d.y, d.z, d.w};
        float tv[4] = {t.x, t.y, t.z, t.w};
        int c = c0;
#pragma unroll
        for (int j = 0; j < 4; j++) {
            bool cont = (c == 0) | ((unsigned)(c - 55) <= 2u);
            if (cont) {
                float df = dv[j] - tv[j];
                mse  = fmaf(df, df, mse);
                dotc = fmaf(dv[j], tv[j], dotc);   // subtract later
            }
            if (++c == NCOLS) c = 0;
        }
    }
}

// ---------------- fused kernel ---------------------------------------------
__global__ void __launch_bounds__(TPB, 8)
k_fused(const float4* __restrict__ e4,
        const float* __restrict__ dec, const float* __restrict__ tru,
        float* __restrict__ out, int B) {
    __shared__ __half smh[TILE * NCOLS];       // 25344 B (tile role)
    __shared__ float wr[3][TPB / 32];
    __shared__ int   s_last;
    __shared__ float s_mn[4][10], s_mx[4][10]; // prep role
    __shared__ unsigned sh[200];
    __shared__ float smn[10], swid[10];

    const int t = threadIdx.x, lane = t & 31, w = t >> 5;

    if (blockIdx.x < NPREP) {
        // ================= PREP ROLE =================
        const int stride = NPREP * TPB;
        const int gbase  = blockIdx.x * TPB + t;

        // phase A: per-column min/max of encoded[:, 0:10], 2 rows per iter
        float mn[10], mx[10];
        const float INF = __int_as_float(0x7f800000);
#pragma unroll
        for (int i = 0; i < 10; i++) { mn[i] = INF; mx[i] = -INF; }
        for (int r = gbase; r < B; r += 2 * stride) {
            float4 a0 = e4[3*r], b0 = e4[3*r+1], c0 = e4[3*r+2];
            int r1 = r + stride;
            bool ok1 = r1 < B;
            float4 a1, b1, c1;
            if (ok1) { a1 = e4[3*r1]; b1 = e4[3*r1+1]; c1 = e4[3*r1+2]; }
            float v0[10] = {a0.x,a0.y,a0.z,a0.w,b0.x,b0.y,b0.z,b0.w,c0.x,c0.y};
#pragma unroll
            for (int i = 0; i < 10; i++) {
                mn[i] = fminf(mn[i], v0[i]);
                mx[i] = fmaxf(mx[i], v0[i]);
            }
            if (ok1) {
                float v1[10] = {a1.x,a1.y,a1.z,a1.w,b1.x,b1.y,b1.z,b1.w,c1.x,c1.y};
#pragma unroll
                for (int i = 0; i < 10; i++) {
                    mn[i] = fminf(mn[i], v1[i]);
                    mx[i] = fmaxf(mx[i], v1[i]);
                }
            }
        }
#pragma unroll
        for (int i = 0; i < 10; i++) {
#pragma unroll
            for (int o = 16; o > 0; o >>= 1) {
                mn[i] = fminf(mn[i], __shfl_xor_sync(0xFFFFFFFFu, mn[i], o));
                mx[i] = fmaxf(mx[i], __shfl_xor_sync(0xFFFFFFFFu, mx[i], o));
            }
        }
        if (lane == 0) {
#pragma unroll
            for (int i = 0; i < 10; i++) { s_mn[w][i] = mn[i]; s_mx[w][i] = mx[i]; }
        }
        for (int j = t; j < 200; j += TPB) sh[j] = 0u;      // FIX: full 200 bins
        __syncthreads();
        if (t < 10) {
            float m = s_mn[0][t], x = s_mx[0][t];
#pragma unroll
            for (int ww = 1; ww < 4; ww++) { m = fminf(m, s_mn[ww][t]); x = fmaxf(x, s_mx[ww][t]); }
            atomicMax(&gz.cominkey[t], ~f2key(m));
            atomicMax(&gz.maxkey[t],    f2key(x));
        }

        // sync among the NPREP prep CTAs only
        __threadfence();
        __syncthreads();
        if (t == 0) {
            atomicAdd(&gz.done[0], 1u);
            while (atomicAdd(&gz.done[0], 0u) < (unsigned)NPREP) __nanosleep(64);
        }
        __syncthreads();
        __threadfence();

        // phase B: histogram with warp-aggregated shared atomics
        if (t < 10) {
            float m = key2f(~gz.cominkey[t]);
            float x = key2f( gz.maxkey[t]);
            smn[t]  = m;
            swid[t] = fmaxf(x - m, 1e-12f);
        }
        __syncthreads();

        const int B_al = B & ~31;
        for (int r = gbase; r < B_al; r += stride) {
            float4 a = e4[3*r], b = e4[3*r+1], c = e4[3*r+2];
            unsigned base = (c.w == 0.0f) ? 0u : 100u;   // col 11 = sex
            float v[10] = {a.x,a.y,a.z,a.w,b.x,b.y,b.z,b.w,c.x,c.y};
#pragma unroll
            for (int i = 0; i < 10; i++) {
                float tt = (v[i] - smn[i]) / swid[i] * 10.0f;   // jnp op order
                int bi = (int)floorf(tt);
                bi = bi < 0 ? 0 : (bi > 9 ? 9 : bi);
                unsigned key = base + (unsigned)(i * 10 + bi);
                unsigned msk = __match_any_sync(0xFFFFFFFFu, key);
                if ((msk & ((1u << lane) - 1u)) == 0u)
                    atomicAdd(&sh[key], (unsigned)__popc(msk));
            }
        }
        for (int r = B_al + gbase; r < B; r += stride) {
            float4 a = e4[3*r], b = e4[3*r+1], c = e4[3*r+2];
            unsigned base = (c.w == 0.0f) ? 0u : 100u;
            float v[10] = {a.x,a.y,a.z,a.w,b.x,b.y,b.z,b.w,c.x,c.y};
#pragma unroll
            for (int i = 0; i < 10; i++) {
                float tt = (v[i] - smn[i]) / swid[i] * 10.0f;
                int bi = (int)floorf(tt);
                bi = bi < 0 ? 0 : (bi > 9 ? 9 : bi);
                atomicAdd(&sh[base + (unsigned)(i * 10 + bi)], 1u);
            }
        }
        __syncthreads();
        for (int j = t; j < 200; j += TPB)                  // FIX: flush all 200 bins
            if (sh[j]) atomicAdd(&gz.hist[j], sh[j]);
        __threadfence();
        __syncthreads();
        if (t == 0) atomicAdd(&gz.done[2], 1u);   // hist ticket
        return;
    }

    // ================= TILE ROLE =================
    const int tileIdx = blockIdx.x - NPREP;
    const int NT      = gridDim.x - NPREP;
    const int r0   = tileIdx * TILE;
    const int rows = min(TILE, B - r0);
    const int nflt = rows * NCOLS;
    const int n4   = nflt >> 2;
    const size_t ebase = (size_t)r0 * NCOLS;
    const float4* d4 = (const float4*)(dec + ebase);
    const float4* t4 = (const float4*)(tru + ebase);

    float dot0 = 0.f, dot1 = 0.f, a_mse = 0.f, dotc = 0.f;

    // columns: element 4*(tid + j*TPB): +17 mod 99 per j, +34 per 2-pair stage
    int cb = (4 * t) % NCOLS;
    const int NS = n4 / (2 * TPB);           // full 2-pair stages

    float4 da0, ta0, da1, ta1, db0, tb0, db1, tb1;
    int ia = t;
    if (NS > 0) {
        da0 = d4[ia];       ta0 = t4[ia];
        da1 = d4[ia + TPB]; ta1 = t4[ia + TPB];
    }
    for (int s = 0; s < NS; s += 2) {
        const int ib = ia + 2 * TPB;
        const bool hb = (s + 1) < NS;
        if (hb) { db0 = d4[ib]; tb0 = t4[ib]; db1 = d4[ib + TPB]; tb1 = t4[ib + TPB]; }
        consume(da0, ta0, cb,              smh, ia,       dot0, dot1, a_mse, dotc);
        consume(da1, ta1, wrap99(cb + 17), smh, ia + TPB, dot0, dot1, a_mse, dotc);
        cb = wrap99(cb + 34);
        if (!hb) break;
        const int ic = ib + 2 * TPB;
        const bool hc = (s + 2) < NS;
        if (hc) { da0 = d4[ic]; ta0 = t4[ic]; da1 = d4[ic + TPB]; ta1 = t4[ic + TPB]; }
        consume(db0, tb0, cb,              smh, ib,       dot0, dot1, a_mse, dotc);
        consume(db1, tb1, wrap99(cb + 17), smh, ib + TPB, dot0, dot1, a_mse, dotc);
        cb = wrap99(cb + 34);
        ia = ic;
    }
    for (int i = NS * 2 * TPB + t; i < n4; i += TPB) {
        consume(d4[i], t4[i], (4 * i) % NCOLS, smh, i, dot0, dot1, a_mse, dotc);
    }
    for (int e = (n4 << 2) + t; e < nflt; e += TPB) {   // float tail
        float d = dec[ebase + e], tt = tru[ebase + e];
        smh[e] = __float2half_rn(d);
        int c = e % NCOLS;
        bool cont = (c == 0) | ((unsigned)(c - 55) <= 2u);
        dot0 = fmaf(d, tt, dot0);
        if (cont) {
            float df = d - tt;
            a_mse = fmaf(df, df, a_mse);
            dotc  = fmaf(d, tt, dotc);
        }
    }
    __syncthreads();

    // phase 2: one thread per row, 8 block-LSEs from fp16 smem
    float a_lse = 0.f;
    if (t < rows) {
        const __half* row = smh + t * NCOLS;
        a_lse += lse_blk_h< 1,  8>(row);
        a_lse += lse_blk_h< 8, 24>(row);
        a_lse += lse_blk_h<24, 31>(row);
        a_lse += lse_blk_h<31, 45>(row);
        a_lse += lse_blk_h<45, 51>(row);
        a_lse += lse_blk_h<51, 53>(row);
        a_lse += lse_blk_h<53, 55>(row);
        a_lse += lse_blk_h<58, 99>(row);
    }

    // block reduce -> double global atomics
    float a_dot = (dot0 + dot1) - dotc;
#pragma unroll
    for (int o = 16; o > 0; o >>= 1) {
        a_mse += __shfl_xor_sync(0xFFFFFFFFu, a_mse, o);
        a_dot += __shfl_xor_sync(0xFFFFFFFFu, a_dot, o);
        a_lse += __shfl_xor_sync(0xFFFFFFFFu, a_lse, o);
    }
    if (lane == 0) { wr[0][w] = a_mse; wr[1][w] = a_dot; wr[2][w] = a_lse; }
    __syncthreads();
    if (t == 0) {
        float m = 0.f, d = 0.f, l = 0.f;
#pragma unroll
        for (int k = 0; k < TPB / 32; k++) { m += wr[0][k]; d += wr[1][k]; l += wr[2][k]; }
        atomicAdd(&gz.acc[0], (double)m);
        atomicAdd(&gz.acc[1], (double)d);
        atomicAdd(&gz.acc[2], (double)l);
        __threadfence();
        unsigned tk = atomicAdd(&gz.done[1], 1u);
        s_last = (tk == (unsigned)(NT - 1)) ? 1 : 0;
        if (s_last) {   // wait for prep histogram tickets
            while (atomicAdd(&gz.done[2], 0u) < (unsigned)NPREP) __nanosleep(64);
        }
    }
    __syncthreads();

    // last tile CTA finalizes (double precision, 32 lanes)
    if (s_last && t < 32) {
        __threadfence();
        int lane32 = t;
        double mcnt = (lane32 < 10) ? (double)gz.hist[lane32]       : 0.0;
        double fcnt = (lane32 < 10) ? (double)gz.hist[100 + lane32] : 0.0;
#pragma unroll
        for (int o = 16; o > 0; o >>= 1) {
            mcnt += __shfl_xor_sync(0xFFFFFFFFu, mcnt, o);
            fcnt += __shfl_xor_sync(0xFFFFFFFFu, fcnt, o);
        }
        double mc = fmax(mcnt, 1.0), fc = fmax(fcnt, 1.0);
        double kld = 0.0;
#pragma unroll
        for (int k = 0; k < 4; k++) {
            int b = k * 32 + lane32;
            if (b < 100) {
                double p = (double)gz.hist[b] / mc;
                double q = (double)gz.hist[100 + b] / fc;
                if (p > 0.0 && q > 0.0) kld += p * log(p / q);
            }
        }
#pragma unroll
        for (int o = 16; o > 0; o >>= 1)
            kld += __shfl_xor_sync(0xFFFFFFFFu, kld, o);
        if (lane32 == 0) {
            double mseS = atomicAdd(&gz.acc[0], 0.0);
            double dotS = atomicAdd(&gz.acc[1], 0.0);
            double lseS = atomicAdd(&gz.acc[2], 0.0);
            double fB   = (double)B;
            double mse  = mseS / fB;
            double ce   = (lseS - dotS) / fB;
            double akld = 0.5 * kld;
            out[0] = (float)(0.5 * (mse + ce) + akld);
            out[1] = (float)mse;
            out[2] = (float)ce;
            out[3] = (float)akld;
        }
    }
}

// ---------------- launcher ----------------
extern "C" void kernel_launch(void* const* d_in, const int* in_sizes, int n_in,
                              void* d_out, int out_size) {
    const float* enc = (const float*)d_in[0];   // [B,12]
    const float* dec = (const float*)d_in[1];   // [B,99]
    const float* tru = (const float*)d_in[2];   // [B,99]
    const int B = in_sizes[1] / NCOLS;
    float* out = (float*)d_out;

    void* pz = nullptr;
    cudaGetSymbolAddress(&pz, gz);
    cudaMemsetAsync(pz, 0, sizeof(Zeros), 0);

    cudaFuncSetAttribute(k_fused, cudaFuncAttributePreferredSharedMemoryCarveout, 100);

    const int NT   = (B + TILE - 1) / TILE;
    const int grid = NPREP + NT;
    k_fused<<<grid, TPB>>>((const float4*)enc, dec, tru, out, B);
}